// round 1
// baseline (speedup 1.0000x reference)
#include <cuda_runtime.h>
#include <math.h>

// Problem constants
#define BB 4
#define SS 2048
#define DD 1024
#define HH 16
#define HD 64
#define LOG2E 1.4426950408889634f

// Scratch (allocation-free rule: __device__ globals)
__device__ float g_qkv[(size_t)BB * SS * 3 * DD];   // [B,S,3D]
__device__ float g_y[(size_t)BB * SS * DD];         // [B,S,D] attention output

// ---------------------------------------------------------------------------
// SGEMM: C[M,N] = A[M,K] @ B[K,N] + bias[N]
// 128x128x8 block tile, 8x8 thread tile, 256 threads.
// ---------------------------------------------------------------------------
__global__ __launch_bounds__(256) void sgemm_bias(
    const float* __restrict__ A, const float* __restrict__ B,
    const float* __restrict__ bias, float* __restrict__ C,
    int M, int N, int K)
{
    __shared__ float As[8][128];   // transposed A tile: As[k][m]
    __shared__ float Bs[8][128];   // Bs[k][n]

    const int tid = threadIdx.x;
    const int ty = tid >> 4;       // 0..15
    const int tx = tid & 15;       // 0..15
    const int bm = blockIdx.y;
    const int bn = blockIdx.x;

    const int arow = tid >> 1;          // 0..127
    const int acol4 = (tid & 1) * 4;    // 0 or 4
    const int brow = tid >> 5;          // 0..7
    const int bcol4 = (tid & 31) * 4;   // 0..124

    const float* Aptr = A + (size_t)(bm * 128) * K;
    const float* Bptr = B + (size_t)bn * 128;

    float acc[8][8];
#pragma unroll
    for (int i = 0; i < 8; i++)
#pragma unroll
        for (int j = 0; j < 8; j++) acc[i][j] = 0.0f;

    for (int k0 = 0; k0 < K; k0 += 8) {
        float4 av = *(const float4*)(Aptr + (size_t)arow * K + k0 + acol4);
        As[acol4 + 0][arow] = av.x;
        As[acol4 + 1][arow] = av.y;
        As[acol4 + 2][arow] = av.z;
        As[acol4 + 3][arow] = av.w;
        float4 bv = *(const float4*)(Bptr + (size_t)(k0 + brow) * N + bcol4);
        *(float4*)&Bs[brow][bcol4] = bv;
        __syncthreads();

#pragma unroll
        for (int k = 0; k < 8; k++) {
            float a[8], b[8];
            *(float4*)(a + 0) = *(float4*)&As[k][ty * 8 + 0];
            *(float4*)(a + 4) = *(float4*)&As[k][ty * 8 + 4];
            *(float4*)(b + 0) = *(float4*)&Bs[k][tx * 8 + 0];
            *(float4*)(b + 4) = *(float4*)&Bs[k][tx * 8 + 4];
#pragma unroll
            for (int i = 0; i < 8; i++)
#pragma unroll
                for (int j = 0; j < 8; j++)
                    acc[i][j] = fmaf(a[i], b[j], acc[i][j]);
        }
        __syncthreads();
    }

    const int crow = bm * 128 + ty * 8;
    const int ccol = bn * 128 + tx * 8;
#pragma unroll
    for (int i = 0; i < 8; i++) {
        float* crow_p = C + (size_t)(crow + i) * N + ccol;
#pragma unroll
        for (int j = 0; j < 8; j++)
            crow_p[j] = acc[i][j] + bias[ccol + j];
    }
}

// ---------------------------------------------------------------------------
// Causal flash attention, fp32, online softmax.
// Grid: (S/64, H, B). 256 threads = 16x16, each owns 4 q-rows x 4 cols.
// Dynamic smem: Qs/Kt/Vs/Ps, each [64][68] floats = 69632 bytes total.
// ---------------------------------------------------------------------------
#define SMP 68   // padded row stride in floats

__global__ __launch_bounds__(256) void flash_attn_kernel(float* __restrict__ y_out)
{
    extern __shared__ float sm[];
    float* Qs = sm;               // Qs[r][d]   r=q row in tile, d=head dim
    float* Kt = sm + 64 * SMP;    // Kt[d][j]   j=kv row in tile (transposed)
    float* Vs = sm + 2 * 64 * SMP;// Vs[j][d]
    float* Ps = sm + 3 * 64 * SMP;// Ps[r][j]

    const int tid = threadIdx.x;
    const int ty = tid >> 4;   // 0..15 -> q rows ty*4..ty*4+3
    const int tx = tid & 15;   // 0..15 -> cols tx*4..tx*4+3
    const int qt = blockIdx.x;
    const int h  = blockIdx.y;
    const int b  = blockIdx.z;
    const int q0 = qt * 64;

    const float* qkv = g_qkv;
    const size_t tokbase = (size_t)b * SS * 3 * DD;

    // Load Q tile [64 rows x 64 dims]
#pragma unroll
    for (int i = 0; i < 4; i++) {
        int f = tid + i * 256;
        int r = f >> 4;
        int d4 = (f & 15) * 4;
        float4 v = *(const float4*)(qkv + tokbase + (size_t)(q0 + r) * (3 * DD) + h * HD + d4);
        *(float4*)&Qs[r * SMP + d4] = v;
    }

    float m[4], l[4], o[4][4];
#pragma unroll
    for (int rr = 0; rr < 4; rr++) {
        m[rr] = -1e30f; l[rr] = 0.0f;
#pragma unroll
        for (int cc = 0; cc < 4; cc++) o[rr][cc] = 0.0f;
    }
    const float scale = 0.125f;  // 1/sqrt(64)

    for (int kt = 0; kt <= qt; kt++) {
        const int k0 = kt * 64;
        __syncthreads();  // previous PV pass done before overwriting Kt/Vs

        // Load K (transposed) and V tiles
#pragma unroll
        for (int i = 0; i < 4; i++) {
            int f = tid + i * 256;
            int j = f >> 4;
            int d4 = (f & 15) * 4;
            const float* kp = qkv + tokbase + (size_t)(k0 + j) * (3 * DD) + DD + h * HD + d4;
            float4 kv = *(const float4*)kp;
            Kt[(d4 + 0) * SMP + j] = kv.x;
            Kt[(d4 + 1) * SMP + j] = kv.y;
            Kt[(d4 + 2) * SMP + j] = kv.z;
            Kt[(d4 + 3) * SMP + j] = kv.w;
            float4 vv = *(const float4*)(kp + DD);  // v = k + D offset
            *(float4*)&Vs[j * SMP + d4] = vv;
        }
        __syncthreads();

        // S = Q @ K^T  (4x4 frag per thread)
        float s[4][4];
#pragma unroll
        for (int rr = 0; rr < 4; rr++)
#pragma unroll
            for (int cc = 0; cc < 4; cc++) s[rr][cc] = 0.0f;

#pragma unroll 4
        for (int d = 0; d < 64; d += 4) {
            float qr[4][4], kr[4][4];
#pragma unroll
            for (int rr = 0; rr < 4; rr++)
                *(float4*)qr[rr] = *(float4*)&Qs[(ty * 4 + rr) * SMP + d];
#pragma unroll
            for (int u = 0; u < 4; u++)
                *(float4*)kr[u] = *(float4*)&Kt[(d + u) * SMP + tx * 4];
#pragma unroll
            for (int rr = 0; rr < 4; rr++)
#pragma unroll
                for (int u = 0; u < 4; u++)
#pragma unroll
                    for (int cc = 0; cc < 4; cc++)
                        s[rr][cc] = fmaf(qr[rr][u], kr[u][cc], s[rr][cc]);
        }

        // scale + causal mask (only diagonal tile needs masking)
        const bool diag = (kt == qt);
#pragma unroll
        for (int rr = 0; rr < 4; rr++) {
            const int qi = q0 + ty * 4 + rr;
#pragma unroll
            for (int cc = 0; cc < 4; cc++) {
                float v = s[rr][cc] * scale;
                if (diag && (k0 + tx * 4 + cc > qi)) v = -1e30f;
                s[rr][cc] = v;
            }
        }

        // online softmax per row (row spread over 16 lanes of a half-warp)
#pragma unroll
        for (int rr = 0; rr < 4; rr++) {
            float mloc = fmaxf(fmaxf(s[rr][0], s[rr][1]), fmaxf(s[rr][2], s[rr][3]));
#pragma unroll
            for (int off = 8; off >= 1; off >>= 1)
                mloc = fmaxf(mloc, __shfl_xor_sync(0xffffffffu, mloc, off));
            const float mnew = fmaxf(m[rr], mloc);
            const float fct = exp2f((m[rr] - mnew) * LOG2E);
            float psum = 0.0f;
#pragma unroll
            for (int cc = 0; cc < 4; cc++) {
                float p = exp2f((s[rr][cc] - mnew) * LOG2E);
                s[rr][cc] = p;
                psum += p;
            }
#pragma unroll
            for (int off = 8; off >= 1; off >>= 1)
                psum += __shfl_xor_sync(0xffffffffu, psum, off);
            l[rr] = l[rr] * fct + psum;
            m[rr] = mnew;
#pragma unroll
            for (int cc = 0; cc < 4; cc++) o[rr][cc] *= fct;
            *(float4*)&Ps[(ty * 4 + rr) * SMP + tx * 4] =
                make_float4(s[rr][0], s[rr][1], s[rr][2], s[rr][3]);
        }
        __syncthreads();

        // O += P @ V
#pragma unroll 4
        for (int k = 0; k < 64; k += 4) {
            float pr[4][4], vr[4][4];
#pragma unroll
            for (int rr = 0; rr < 4; rr++)
                *(float4*)pr[rr] = *(float4*)&Ps[(ty * 4 + rr) * SMP + k];
#pragma unroll
            for (int u = 0; u < 4; u++)
                *(float4*)vr[u] = *(float4*)&Vs[(k + u) * SMP + tx * 4];
#pragma unroll
            for (int rr = 0; rr < 4; rr++)
#pragma unroll
                for (int u = 0; u < 4; u++)
#pragma unroll
                    for (int cc = 0; cc < 4; cc++)
                        o[rr][cc] = fmaf(pr[rr][u], vr[u][cc], o[rr][cc]);
        }
    }

    // epilogue: normalize + write y[B,S,D] at head slice
#pragma unroll
    for (int rr = 0; rr < 4; rr++) {
        const float inv = 1.0f / l[rr];
        float* yp = y_out + ((size_t)b * SS + q0 + ty * 4 + rr) * DD + h * HD + tx * 4;
        float4 ov = make_float4(o[rr][0] * inv, o[rr][1] * inv, o[rr][2] * inv, o[rr][3] * inv);
        *(float4*)yp = ov;
    }
}

// ---------------------------------------------------------------------------
// Launch
// ---------------------------------------------------------------------------
extern "C" void kernel_launch(void* const* d_in, const int* in_sizes, int n_in,
                              void* d_out, int out_size)
{
    (void)in_sizes; (void)n_in; (void)out_size;
    const float* x      = (const float*)d_in[0];
    const float* W_attn = (const float*)d_in[1];
    const float* b_attn = (const float*)d_in[2];
    const float* W_proj = (const float*)d_in[3];
    const float* b_proj = (const float*)d_in[4];
    float* out = (float*)d_out;

    float* qkv_ptr = nullptr;
    float* y_ptr = nullptr;
    cudaGetSymbolAddress((void**)&qkv_ptr, g_qkv);
    cudaGetSymbolAddress((void**)&y_ptr, g_y);

    const int M = BB * SS;           // 8192
    const int smem_flash = 4 * 64 * SMP * sizeof(float);  // 69632 B
    cudaFuncSetAttribute(flash_attn_kernel,
                         cudaFuncAttributeMaxDynamicSharedMemorySize, smem_flash);

    // 1) QKV projection: [8192,1024] @ [1024,3072] + b
    {
        dim3 grid(3 * DD / 128, M / 128);
        sgemm_bias<<<grid, 256>>>(x, W_attn, b_attn, qkv_ptr, M, 3 * DD, DD);
    }
    // 2) Causal flash attention
    {
        dim3 grid(SS / 64, HH, BB);
        flash_attn_kernel<<<grid, 256, smem_flash>>>(y_ptr);
    }
    // 3) Output projection: [8192,1024] @ [1024,1024] + b
    {
        dim3 grid(DD / 128, M / 128);
        sgemm_bias<<<grid, 256>>>(y_ptr, W_proj, b_proj, out, M, DD, DD);
    }
}

// round 3
// speedup vs baseline: 1.7841x; 1.7841x over previous
#include <cuda_runtime.h>
#include <math.h>
#include <stdint.h>

// Problem constants
#define BB 4
#define SS 2048
#define DD 1024
#define HH 16
#define HD 64
#define LOG2E 1.4426950408889634f

// Scratch (__device__ globals per allocation rules)
__device__ float g_qkv[(size_t)BB * SS * 3 * DD];   // [B,S,3D]
__device__ float g_y[(size_t)BB * SS * DD];         // [B,S,D]

__device__ __forceinline__ uint32_t cvt_tf32(float f) {
    uint32_t r;
    asm("cvt.rna.tf32.f32 %0, %1;" : "=r"(r) : "f"(f));
    return r;
}

// ---------------------------------------------------------------------------
// TF32 tensor-core GEMM via mma.sync (sm_80 path, works on base sm_103 target)
// C[M, Ntot] = A[M, 1024] @ B[1024, Ntot] + bias
// CTA tile 128x128, k-tile 16, 256 threads = 8 warps (2 x 4), warp tile 64x32.
// ---------------------------------------------------------------------------
#define GK 1024
#define KT 16
#define NKT (GK / KT)     // 64
#define SST 136           // smem row stride (floats): conflict-free frag loads

__global__ __launch_bounds__(256) void hmma_gemm(
    const float* __restrict__ A, const float* __restrict__ B,
    const float* __restrict__ bias, float* __restrict__ C, int Ntot)
{
    // [stage][k][m or n], stride SST
    __shared__ float As[2][KT][SST];
    __shared__ float Bs[2][KT][SST];

    const int tid = threadIdx.x;
    const int wid = tid >> 5;
    const int lane = tid & 31;
    const int warp_m = wid & 1;        // 0..1 -> 64 rows each
    const int warp_n = wid >> 1;       // 0..3 -> 32 cols each
    const int bn = blockIdx.x;
    const int bm = blockIdx.y;

    const int lg = lane >> 2;          // 0..7
    const int lq = lane & 3;           // 0..3

    // Global load indexing
    const int a_row = tid >> 1;              // with idx=tid, tid+256: rows 0..127 twice
    // A: idx -> row = idx>>2, kq = (idx&3)*4
    // B: idx -> r = idx>>5, n4 = (idx&31)*4

    float acc[4][4][4];
#pragma unroll
    for (int mt = 0; mt < 4; mt++)
#pragma unroll
        for (int nt = 0; nt < 4; nt++)
#pragma unroll
            for (int i = 0; i < 4; i++) acc[mt][nt][i] = 0.0f;

    const float* Abase = A + (size_t)(bm * 128) * GK;
    const float* Bbase = B + bn * 128;

    float4 a_pf[2], b_pf[2];

    // --- prologue: load k-tile 0 ---
#pragma unroll
    for (int i = 0; i < 2; i++) {
        const int idx = tid + i * 256;
        const int row = idx >> 2, kq = (idx & 3) * 4;
        a_pf[i] = *(const float4*)(Abase + (size_t)row * GK + kq);
        const int r = idx >> 5, n4 = (idx & 31) * 4;
        b_pf[i] = *(const float4*)(Bbase + (size_t)r * Ntot + n4);
    }
#pragma unroll
    for (int i = 0; i < 2; i++) {
        const int idx = tid + i * 256;
        const int row = idx >> 2, kq = (idx & 3) * 4;
        As[0][kq + 0][row] = __uint_as_float(cvt_tf32(a_pf[i].x));
        As[0][kq + 1][row] = __uint_as_float(cvt_tf32(a_pf[i].y));
        As[0][kq + 2][row] = __uint_as_float(cvt_tf32(a_pf[i].z));
        As[0][kq + 3][row] = __uint_as_float(cvt_tf32(a_pf[i].w));
        const int r = idx >> 5, n4 = (idx & 31) * 4;
        float4 bv;
        bv.x = __uint_as_float(cvt_tf32(b_pf[i].x));
        bv.y = __uint_as_float(cvt_tf32(b_pf[i].y));
        bv.z = __uint_as_float(cvt_tf32(b_pf[i].z));
        bv.w = __uint_as_float(cvt_tf32(b_pf[i].w));
        *(float4*)&Bs[0][r][n4] = bv;
    }
    __syncthreads();

    for (int kt = 0; kt < NKT; kt++) {
        const int cur = kt & 1;

        // prefetch next tile into registers
        if (kt + 1 < NKT) {
#pragma unroll
            for (int i = 0; i < 2; i++) {
                const int idx = tid + i * 256;
                const int row = idx >> 2, kq = (idx & 3) * 4;
                a_pf[i] = *(const float4*)(Abase + (size_t)row * GK + (kt + 1) * KT + kq);
                const int r = idx >> 5, n4 = (idx & 31) * 4;
                b_pf[i] = *(const float4*)(Bbase + (size_t)((kt + 1) * KT + r) * Ntot + n4);
            }
        }

        // compute: two k8 steps
#pragma unroll
        for (int k0 = 0; k0 < KT; k0 += 8) {
            uint32_t af[4][4];   // [mt][reg]
            uint32_t bf[4][2];   // [nt][reg]
#pragma unroll
            for (int mt = 0; mt < 4; mt++) {
                const int mb = warp_m * 64 + mt * 16;
                af[mt][0] = __float_as_uint(As[cur][k0 + lq]    [mb + lg]);
                af[mt][1] = __float_as_uint(As[cur][k0 + lq]    [mb + 8 + lg]);
                af[mt][2] = __float_as_uint(As[cur][k0 + lq + 4][mb + lg]);
                af[mt][3] = __float_as_uint(As[cur][k0 + lq + 4][mb + 8 + lg]);
            }
#pragma unroll
            for (int nt = 0; nt < 4; nt++) {
                const int nb = warp_n * 32 + nt * 8;
                bf[nt][0] = __float_as_uint(Bs[cur][k0 + lq]    [nb + lg]);
                bf[nt][1] = __float_as_uint(Bs[cur][k0 + lq + 4][nb + lg]);
            }
#pragma unroll
            for (int mt = 0; mt < 4; mt++)
#pragma unroll
                for (int nt = 0; nt < 4; nt++) {
                    asm volatile(
                        "mma.sync.aligned.m16n8k8.row.col.f32.tf32.tf32.f32 "
                        "{%0,%1,%2,%3}, {%4,%5,%6,%7}, {%8,%9}, {%0,%1,%2,%3};"
                        : "+f"(acc[mt][nt][0]), "+f"(acc[mt][nt][1]),
                          "+f"(acc[mt][nt][2]), "+f"(acc[mt][nt][3])
                        : "r"(af[mt][0]), "r"(af[mt][1]), "r"(af[mt][2]), "r"(af[mt][3]),
                          "r"(bf[nt][0]), "r"(bf[nt][1]));
                }
        }

        // store prefetched tile
        if (kt + 1 < NKT) {
            const int nxt = cur ^ 1;
#pragma unroll
            for (int i = 0; i < 2; i++) {
                const int idx = tid + i * 256;
                const int row = idx >> 2, kq = (idx & 3) * 4;
                As[nxt][kq + 0][row] = __uint_as_float(cvt_tf32(a_pf[i].x));
                As[nxt][kq + 1][row] = __uint_as_float(cvt_tf32(a_pf[i].y));
                As[nxt][kq + 2][row] = __uint_as_float(cvt_tf32(a_pf[i].z));
                As[nxt][kq + 3][row] = __uint_as_float(cvt_tf32(a_pf[i].w));
                const int r = idx >> 5, n4 = (idx & 31) * 4;
                float4 bv;
                bv.x = __uint_as_float(cvt_tf32(b_pf[i].x));
                bv.y = __uint_as_float(cvt_tf32(b_pf[i].y));
                bv.z = __uint_as_float(cvt_tf32(b_pf[i].z));
                bv.w = __uint_as_float(cvt_tf32(b_pf[i].w));
                *(float4*)&Bs[nxt][r][n4] = bv;
            }
            __syncthreads();
        }
    }

    // epilogue: write C + bias
#pragma unroll
    for (int mt = 0; mt < 4; mt++) {
        const int row0 = bm * 128 + warp_m * 64 + mt * 16 + lg;
#pragma unroll
        for (int nt = 0; nt < 4; nt++) {
            const int col = bn * 128 + warp_n * 32 + nt * 8 + 2 * lq;
            const float b0 = bias[col], b1 = bias[col + 1];
            float2 v0 = make_float2(acc[mt][nt][0] + b0, acc[mt][nt][1] + b1);
            float2 v1 = make_float2(acc[mt][nt][2] + b0, acc[mt][nt][3] + b1);
            *(float2*)(C + (size_t)row0 * Ntot + col) = v0;
            *(float2*)(C + (size_t)(row0 + 8) * Ntot + col) = v1;
        }
    }
}

// ---------------------------------------------------------------------------
// Causal flash attention, fp32, online softmax (unchanged — round-1 validated)
// ---------------------------------------------------------------------------
#define SMP 68

__global__ __launch_bounds__(256) void flash_attn_kernel(float* __restrict__ y_out)
{
    extern __shared__ float sm[];
    float* Qs = sm;
    float* Kt = sm + 64 * SMP;
    float* Vs = sm + 2 * 64 * SMP;
    float* Ps = sm + 3 * 64 * SMP;

    const int tid = threadIdx.x;
    const int ty = tid >> 4;
    const int tx = tid & 15;
    const int qt = blockIdx.x;
    const int h  = blockIdx.y;
    const int b  = blockIdx.z;
    const int q0 = qt * 64;

    const float* qkv = g_qkv;
    const size_t tokbase = (size_t)b * SS * 3 * DD;

#pragma unroll
    for (int i = 0; i < 4; i++) {
        int f = tid + i * 256;
        int r = f >> 4;
        int d4 = (f & 15) * 4;
        float4 v = *(const float4*)(qkv + tokbase + (size_t)(q0 + r) * (3 * DD) + h * HD + d4);
        *(float4*)&Qs[r * SMP + d4] = v;
    }

    float m[4], l[4], o[4][4];
#pragma unroll
    for (int rr = 0; rr < 4; rr++) {
        m[rr] = -1e30f; l[rr] = 0.0f;
#pragma unroll
        for (int cc = 0; cc < 4; cc++) o[rr][cc] = 0.0f;
    }
    const float scale = 0.125f;

    for (int kt = 0; kt <= qt; kt++) {
        const int k0 = kt * 64;
        __syncthreads();

#pragma unroll
        for (int i = 0; i < 4; i++) {
            int f = tid + i * 256;
            int j = f >> 4;
            int d4 = (f & 15) * 4;
            const float* kp = qkv + tokbase + (size_t)(k0 + j) * (3 * DD) + DD + h * HD + d4;
            float4 kv = *(const float4*)kp;
            Kt[(d4 + 0) * SMP + j] = kv.x;
            Kt[(d4 + 1) * SMP + j] = kv.y;
            Kt[(d4 + 2) * SMP + j] = kv.z;
            Kt[(d4 + 3) * SMP + j] = kv.w;
            float4 vv = *(const float4*)(kp + DD);
            *(float4*)&Vs[j * SMP + d4] = vv;
        }
        __syncthreads();

        float s[4][4];
#pragma unroll
        for (int rr = 0; rr < 4; rr++)
#pragma unroll
            for (int cc = 0; cc < 4; cc++) s[rr][cc] = 0.0f;

#pragma unroll 4
        for (int d = 0; d < 64; d += 4) {
            float qr[4][4], kr[4][4];
#pragma unroll
            for (int rr = 0; rr < 4; rr++)
                *(float4*)qr[rr] = *(float4*)&Qs[(ty * 4 + rr) * SMP + d];
#pragma unroll
            for (int u = 0; u < 4; u++)
                *(float4*)kr[u] = *(float4*)&Kt[(d + u) * SMP + tx * 4];
#pragma unroll
            for (int rr = 0; rr < 4; rr++)
#pragma unroll
                for (int u = 0; u < 4; u++)
#pragma unroll
                    for (int cc = 0; cc < 4; cc++)
                        s[rr][cc] = fmaf(qr[rr][u], kr[u][cc], s[rr][cc]);
        }

        const bool diag = (kt == qt);
#pragma unroll
        for (int rr = 0; rr < 4; rr++) {
            const int qi = q0 + ty * 4 + rr;
#pragma unroll
            for (int cc = 0; cc < 4; cc++) {
                float v = s[rr][cc] * scale;
                if (diag && (k0 + tx * 4 + cc > qi)) v = -1e30f;
                s[rr][cc] = v;
            }
        }

#pragma unroll
        for (int rr = 0; rr < 4; rr++) {
            float mloc = fmaxf(fmaxf(s[rr][0], s[rr][1]), fmaxf(s[rr][2], s[rr][3]));
#pragma unroll
            for (int off = 8; off >= 1; off >>= 1)
                mloc = fmaxf(mloc, __shfl_xor_sync(0xffffffffu, mloc, off));
            const float mnew = fmaxf(m[rr], mloc);
            const float fct = exp2f((m[rr] - mnew) * LOG2E);
            float psum = 0.0f;
#pragma unroll
            for (int cc = 0; cc < 4; cc++) {
                float p = exp2f((s[rr][cc] - mnew) * LOG2E);
                s[rr][cc] = p;
                psum += p;
            }
#pragma unroll
            for (int off = 8; off >= 1; off >>= 1)
                psum += __shfl_xor_sync(0xffffffffu, psum, off);
            l[rr] = l[rr] * fct + psum;
            m[rr] = mnew;
#pragma unroll
            for (int cc = 0; cc < 4; cc++) o[rr][cc] *= fct;
            *(float4*)&Ps[(ty * 4 + rr) * SMP + tx * 4] =
                make_float4(s[rr][0], s[rr][1], s[rr][2], s[rr][3]);
        }
        __syncthreads();

#pragma unroll 4
        for (int k = 0; k < 64; k += 4) {
            float pr[4][4], vr[4][4];
#pragma unroll
            for (int rr = 0; rr < 4; rr++)
                *(float4*)pr[rr] = *(float4*)&Ps[(ty * 4 + rr) * SMP + k];
#pragma unroll
            for (int u = 0; u < 4; u++)
                *(float4*)vr[u] = *(float4*)&Vs[(k + u) * SMP + tx * 4];
#pragma unroll
            for (int rr = 0; rr < 4; rr++)
#pragma unroll
                for (int u = 0; u < 4; u++)
#pragma unroll
                    for (int cc = 0; cc < 4; cc++)
                        o[rr][cc] = fmaf(pr[rr][u], vr[u][cc], o[rr][cc]);
        }
    }

#pragma unroll
    for (int rr = 0; rr < 4; rr++) {
        const float inv = 1.0f / l[rr];
        float* yp = y_out + ((size_t)b * SS + q0 + ty * 4 + rr) * DD + h * HD + tx * 4;
        float4 ov = make_float4(o[rr][0] * inv, o[rr][1] * inv, o[rr][2] * inv, o[rr][3] * inv);
        *(float4*)yp = ov;
    }
}

// ---------------------------------------------------------------------------
// Launch
// ---------------------------------------------------------------------------
extern "C" void kernel_launch(void* const* d_in, const int* in_sizes, int n_in,
                              void* d_out, int out_size)
{
    (void)in_sizes; (void)n_in; (void)out_size;
    const float* x      = (const float*)d_in[0];
    const float* W_attn = (const float*)d_in[1];
    const float* b_attn = (const float*)d_in[2];
    const float* W_proj = (const float*)d_in[3];
    const float* b_proj = (const float*)d_in[4];
    float* out = (float*)d_out;

    float *qkv_ptr = nullptr, *y_ptr = nullptr;
    cudaGetSymbolAddress((void**)&qkv_ptr, g_qkv);
    cudaGetSymbolAddress((void**)&y_ptr, g_y);

    const int M = BB * SS;  // 8192
    const int smem_flash = 4 * 64 * SMP * sizeof(float);  // 69632
    cudaFuncSetAttribute(flash_attn_kernel,
                         cudaFuncAttributeMaxDynamicSharedMemorySize, smem_flash);

    // 1) QKV projection: [8192,1024] @ [1024,3072] + b  (tf32 mma.sync)
    {
        dim3 grid(3 * DD / 128, M / 128);
        hmma_gemm<<<grid, 256>>>(x, W_attn, b_attn, qkv_ptr, 3 * DD);
    }
    // 2) Causal flash attention (fp32)
    {
        dim3 grid(SS / 64, HH, BB);
        flash_attn_kernel<<<grid, 256, smem_flash>>>(y_ptr);
    }
    // 3) Output projection: [8192,1024] @ [1024,1024] + b  (tf32 mma.sync)
    {
        dim3 grid(DD / 128, M / 128);
        hmma_gemm<<<grid, 256>>>(y_ptr, W_proj, b_proj, out, DD);
    }
}

// round 4
// speedup vs baseline: 2.9121x; 1.6322x over previous
#include <cuda_runtime.h>
#include <math.h>
#include <stdint.h>

// Problem constants
#define BB 4
#define SS 2048
#define DD 1024
#define HH 16
#define HD 64
#define LOG2E 1.4426950408889634f

// Scratch (__device__ globals per allocation rules)
__device__ float g_qkv[(size_t)BB * SS * 3 * DD];   // [B,S,3D]
__device__ float g_y[(size_t)BB * SS * DD];         // [B,S,D]

__device__ __forceinline__ uint32_t cvt_tf32(float f) {
    uint32_t r;
    asm("cvt.rna.tf32.f32 %0, %1;" : "=r"(r) : "f"(f));
    return r;
}

#define MMA_TF32(acc, a0, a1, a2, a3, b0, b1) \
    asm volatile( \
        "mma.sync.aligned.m16n8k8.row.col.f32.tf32.tf32.f32 " \
        "{%0,%1,%2,%3}, {%4,%5,%6,%7}, {%8,%9}, {%0,%1,%2,%3};" \
        : "+f"((acc)[0]), "+f"((acc)[1]), "+f"((acc)[2]), "+f"((acc)[3]) \
        : "r"(a0), "r"(a1), "r"(a2), "r"(a3), "r"(b0), "r"(b1))

// ---------------------------------------------------------------------------
// TF32 tensor-core GEMM via mma.sync  (validated round 3)
// C[M, Ntot] = A[M, 1024] @ B[1024, Ntot] + bias
// ---------------------------------------------------------------------------
#define GK 1024
#define KT 16
#define NKT (GK / KT)
#define SST 136

__global__ __launch_bounds__(256) void hmma_gemm(
    const float* __restrict__ A, const float* __restrict__ B,
    const float* __restrict__ bias, float* __restrict__ C, int Ntot)
{
    __shared__ float As[2][KT][SST];
    __shared__ float Bs[2][KT][SST];

    const int tid = threadIdx.x;
    const int wid = tid >> 5;
    const int lane = tid & 31;
    const int warp_m = wid & 1;
    const int warp_n = wid >> 1;
    const int bn = blockIdx.x;
    const int bm = blockIdx.y;
    const int lg = lane >> 2;
    const int lq = lane & 3;

    float acc[4][4][4];
#pragma unroll
    for (int mt = 0; mt < 4; mt++)
#pragma unroll
        for (int nt = 0; nt < 4; nt++)
#pragma unroll
            for (int i = 0; i < 4; i++) acc[mt][nt][i] = 0.0f;

    const float* Abase = A + (size_t)(bm * 128) * GK;
    const float* Bbase = B + bn * 128;

    float4 a_pf[2], b_pf[2];

#pragma unroll
    for (int i = 0; i < 2; i++) {
        const int idx = tid + i * 256;
        const int row = idx >> 2, kq = (idx & 3) * 4;
        a_pf[i] = *(const float4*)(Abase + (size_t)row * GK + kq);
        const int r = idx >> 5, n4 = (idx & 31) * 4;
        b_pf[i] = *(const float4*)(Bbase + (size_t)r * Ntot + n4);
    }
#pragma unroll
    for (int i = 0; i < 2; i++) {
        const int idx = tid + i * 256;
        const int row = idx >> 2, kq = (idx & 3) * 4;
        As[0][kq + 0][row] = __uint_as_float(cvt_tf32(a_pf[i].x));
        As[0][kq + 1][row] = __uint_as_float(cvt_tf32(a_pf[i].y));
        As[0][kq + 2][row] = __uint_as_float(cvt_tf32(a_pf[i].z));
        As[0][kq + 3][row] = __uint_as_float(cvt_tf32(a_pf[i].w));
        const int r = idx >> 5, n4 = (idx & 31) * 4;
        float4 bv;
        bv.x = __uint_as_float(cvt_tf32(b_pf[i].x));
        bv.y = __uint_as_float(cvt_tf32(b_pf[i].y));
        bv.z = __uint_as_float(cvt_tf32(b_pf[i].z));
        bv.w = __uint_as_float(cvt_tf32(b_pf[i].w));
        *(float4*)&Bs[0][r][n4] = bv;
    }
    __syncthreads();

    for (int kt = 0; kt < NKT; kt++) {
        const int cur = kt & 1;

        if (kt + 1 < NKT) {
#pragma unroll
            for (int i = 0; i < 2; i++) {
                const int idx = tid + i * 256;
                const int row = idx >> 2, kq = (idx & 3) * 4;
                a_pf[i] = *(const float4*)(Abase + (size_t)row * GK + (kt + 1) * KT + kq);
                const int r = idx >> 5, n4 = (idx & 31) * 4;
                b_pf[i] = *(const float4*)(Bbase + (size_t)((kt + 1) * KT + r) * Ntot + n4);
            }
        }

#pragma unroll
        for (int k0 = 0; k0 < KT; k0 += 8) {
            uint32_t af[4][4];
            uint32_t bf[4][2];
#pragma unroll
            for (int mt = 0; mt < 4; mt++) {
                const int mb = warp_m * 64 + mt * 16;
                af[mt][0] = __float_as_uint(As[cur][k0 + lq]    [mb + lg]);
                af[mt][1] = __float_as_uint(As[cur][k0 + lq]    [mb + 8 + lg]);
                af[mt][2] = __float_as_uint(As[cur][k0 + lq + 4][mb + lg]);
                af[mt][3] = __float_as_uint(As[cur][k0 + lq + 4][mb + 8 + lg]);
            }
#pragma unroll
            for (int nt = 0; nt < 4; nt++) {
                const int nb = warp_n * 32 + nt * 8;
                bf[nt][0] = __float_as_uint(Bs[cur][k0 + lq]    [nb + lg]);
                bf[nt][1] = __float_as_uint(Bs[cur][k0 + lq + 4][nb + lg]);
            }
#pragma unroll
            for (int mt = 0; mt < 4; mt++)
#pragma unroll
                for (int nt = 0; nt < 4; nt++)
                    MMA_TF32(acc[mt][nt], af[mt][0], af[mt][1], af[mt][2], af[mt][3],
                             bf[nt][0], bf[nt][1]);
        }

        if (kt + 1 < NKT) {
            const int nxt = cur ^ 1;
#pragma unroll
            for (int i = 0; i < 2; i++) {
                const int idx = tid + i * 256;
                const int row = idx >> 2, kq = (idx & 3) * 4;
                As[nxt][kq + 0][row] = __uint_as_float(cvt_tf32(a_pf[i].x));
                As[nxt][kq + 1][row] = __uint_as_float(cvt_tf32(a_pf[i].y));
                As[nxt][kq + 2][row] = __uint_as_float(cvt_tf32(a_pf[i].z));
                As[nxt][kq + 3][row] = __uint_as_float(cvt_tf32(a_pf[i].w));
                const int r = idx >> 5, n4 = (idx & 31) * 4;
                float4 bv;
                bv.x = __uint_as_float(cvt_tf32(b_pf[i].x));
                bv.y = __uint_as_float(cvt_tf32(b_pf[i].y));
                bv.z = __uint_as_float(cvt_tf32(b_pf[i].z));
                bv.w = __uint_as_float(cvt_tf32(b_pf[i].w));
                *(float4*)&Bs[nxt][r][n4] = bv;
            }
            __syncthreads();
        }
    }

#pragma unroll
    for (int mt = 0; mt < 4; mt++) {
        const int row0 = bm * 128 + warp_m * 64 + mt * 16 + lg;
#pragma unroll
        for (int nt = 0; nt < 4; nt++) {
            const int col = bn * 128 + warp_n * 32 + nt * 8 + 2 * lq;
            const float b0 = bias[col], b1 = bias[col + 1];
            float2 v0 = make_float2(acc[mt][nt][0] + b0, acc[mt][nt][1] + b1);
            float2 v1 = make_float2(acc[mt][nt][2] + b0, acc[mt][nt][3] + b1);
            *(float2*)(C + (size_t)row0 * Ntot + col) = v0;
            *(float2*)(C + (size_t)(row0 + 8) * Ntot + col) = v1;
        }
    }
}

// ---------------------------------------------------------------------------
// Flash attention with tf32 mma.sync.
// Q tile 128 rows (8 warps x m16), kv chunks of 64, HD=64.
// All smem tiles natural row-major, stride 68 -> conflict-free frag loads.
// Grid: (S/128, H, B). 256 threads.
// ---------------------------------------------------------------------------
#define FST 68
#define FLASH_SMEM ((128 * FST + 2 * 64 * FST) * 4)   // 69632 B

__global__ __launch_bounds__(256) void flash_mma_kernel(float* __restrict__ y_out)
{
    extern __shared__ float sm[];
    float* Qs = sm;                 // [128][FST]  (reused as Ps after prologue)
    float* Ks = sm + 128 * FST;     // [64][FST]
    float* Vs = Ks + 64 * FST;      // [64][FST]
    float* Ps = Qs;                 // [128][FST]

    const int tid = threadIdx.x;
    const int wid = tid >> 5;
    const int lane = tid & 31;
    const int lg = lane >> 2;     // 0..7
    const int lq = lane & 3;      // 0..3
    const int mb = wid * 16;      // warp's q-row base within tile

    const int qt = blockIdx.x;
    const int h  = blockIdx.y;
    const int b  = blockIdx.z;
    const int q0 = qt * 128;

    const float* qkv = g_qkv;
    const size_t tokbase = (size_t)b * SS * 3 * DD;

    // --- Load Q tile [128 x 64], tf32-rounded, natural layout ---
#pragma unroll
    for (int i = 0; i < 8; i++) {
        const int idx = tid + i * 256;
        const int r = idx >> 4;
        const int d4 = (idx & 15) * 4;
        float4 v = *(const float4*)(qkv + tokbase + (size_t)(q0 + r) * (3 * DD) + h * HD + d4);
        float4 t;
        t.x = __uint_as_float(cvt_tf32(v.x));
        t.y = __uint_as_float(cvt_tf32(v.y));
        t.z = __uint_as_float(cvt_tf32(v.z));
        t.w = __uint_as_float(cvt_tf32(v.w));
        *(float4*)&Qs[r * FST + d4] = t;
    }
    __syncthreads();

    // --- Hoist Q fragments to registers (reused every chunk) ---
    uint32_t aq[8][4];
#pragma unroll
    for (int k = 0; k < 8; k++) {
        aq[k][0] = __float_as_uint(Qs[(mb + lg) * FST + k * 8 + lq]);
        aq[k][1] = __float_as_uint(Qs[(mb + 8 + lg) * FST + k * 8 + lq]);
        aq[k][2] = __float_as_uint(Qs[(mb + lg) * FST + k * 8 + lq + 4]);
        aq[k][3] = __float_as_uint(Qs[(mb + 8 + lg) * FST + k * 8 + lq + 4]);
    }
    __syncthreads();   // Qs free for reuse as Ps

    float o[8][4];
#pragma unroll
    for (int n = 0; n < 8; n++)
#pragma unroll
        for (int i = 0; i < 4; i++) o[n][i] = 0.0f;
    float m0 = -1e30f, m1 = -1e30f, l0 = 0.0f, l1 = 0.0f;

    const int r0g = q0 + mb + lg;      // global q row (frag row 0)
    const int r1g = r0g + 8;           // frag row 1
    const int nchunks = 2 * qt + 2;
    const float scale = 0.125f;

    for (int c = 0; c < nchunks; c++) {
        const int k0g = c * 64;

        // --- Load K, V chunks [64 x 64], tf32-rounded ---
#pragma unroll
        for (int i = 0; i < 4; i++) {
            const int idx = tid + i * 256;
            const int j = idx >> 4;
            const int d4 = (idx & 15) * 4;
            const float* kp = qkv + tokbase + (size_t)(k0g + j) * (3 * DD) + DD + h * HD + d4;
            float4 kv = *(const float4*)kp;
            float4 vv = *(const float4*)(kp + DD);
            float4 tk, tv;
            tk.x = __uint_as_float(cvt_tf32(kv.x));
            tk.y = __uint_as_float(cvt_tf32(kv.y));
            tk.z = __uint_as_float(cvt_tf32(kv.z));
            tk.w = __uint_as_float(cvt_tf32(kv.w));
            tv.x = __uint_as_float(cvt_tf32(vv.x));
            tv.y = __uint_as_float(cvt_tf32(vv.y));
            tv.z = __uint_as_float(cvt_tf32(vv.z));
            tv.w = __uint_as_float(cvt_tf32(vv.w));
            *(float4*)&Ks[j * FST + d4] = tk;
            *(float4*)&Vs[j * FST + d4] = tv;
        }
        __syncthreads();

        // --- S = Q @ K^T  (B-frag reads K natural: B[k=d][n=j] = K[j][d]) ---
        float s[8][4];
#pragma unroll
        for (int n = 0; n < 8; n++)
#pragma unroll
            for (int i = 0; i < 4; i++) s[n][i] = 0.0f;

#pragma unroll
        for (int n = 0; n < 8; n++) {
            const int jb = n * 8;
#pragma unroll
            for (int k = 0; k < 8; k++) {
                uint32_t b0 = __float_as_uint(Ks[(jb + lg) * FST + k * 8 + lq]);
                uint32_t b1 = __float_as_uint(Ks[(jb + lg) * FST + k * 8 + lq + 4]);
                MMA_TF32(s[n], aq[k][0], aq[k][1], aq[k][2], aq[k][3], b0, b1);
            }
        }

        // --- scale + causal mask (only last two chunks touch the diagonal) ---
        if (c >= 2 * qt) {
#pragma unroll
            for (int n = 0; n < 8; n++) {
                const int col = k0g + n * 8 + 2 * lq;
                s[n][0] = (col     > r0g) ? -1e30f : s[n][0] * scale;
                s[n][1] = (col + 1 > r0g) ? -1e30f : s[n][1] * scale;
                s[n][2] = (col     > r1g) ? -1e30f : s[n][2] * scale;
                s[n][3] = (col + 1 > r1g) ? -1e30f : s[n][3] * scale;
            }
        } else {
#pragma unroll
            for (int n = 0; n < 8; n++)
#pragma unroll
                for (int i = 0; i < 4; i++) s[n][i] *= scale;
        }

        // --- online softmax (rows lg / lg+8; reduce across quad lanes) ---
        float mx0 = -1e30f, mx1 = -1e30f;
#pragma unroll
        for (int n = 0; n < 8; n++) {
            mx0 = fmaxf(mx0, fmaxf(s[n][0], s[n][1]));
            mx1 = fmaxf(mx1, fmaxf(s[n][2], s[n][3]));
        }
        mx0 = fmaxf(mx0, __shfl_xor_sync(0xffffffffu, mx0, 1));
        mx0 = fmaxf(mx0, __shfl_xor_sync(0xffffffffu, mx0, 2));
        mx1 = fmaxf(mx1, __shfl_xor_sync(0xffffffffu, mx1, 1));
        mx1 = fmaxf(mx1, __shfl_xor_sync(0xffffffffu, mx1, 2));

        const float mn0 = fmaxf(m0, mx0);
        const float mn1 = fmaxf(m1, mx1);
        const float f0 = exp2f((m0 - mn0) * LOG2E);
        const float f1 = exp2f((m1 - mn1) * LOG2E);

        float sum0 = 0.0f, sum1 = 0.0f;
#pragma unroll
        for (int n = 0; n < 8; n++) {
            float p0 = exp2f((s[n][0] - mn0) * LOG2E);
            float p1 = exp2f((s[n][1] - mn0) * LOG2E);
            float p2 = exp2f((s[n][2] - mn1) * LOG2E);
            float p3 = exp2f((s[n][3] - mn1) * LOG2E);
            sum0 += p0 + p1;
            sum1 += p2 + p3;
            // store P (tf32-rounded) to warp-private rows of Ps
            float2 w0 = make_float2(__uint_as_float(cvt_tf32(p0)), __uint_as_float(cvt_tf32(p1)));
            float2 w1 = make_float2(__uint_as_float(cvt_tf32(p2)), __uint_as_float(cvt_tf32(p3)));
            *(float2*)&Ps[(mb + lg) * FST + n * 8 + 2 * lq] = w0;
            *(float2*)&Ps[(mb + 8 + lg) * FST + n * 8 + 2 * lq] = w1;
        }
        sum0 += __shfl_xor_sync(0xffffffffu, sum0, 1);
        sum0 += __shfl_xor_sync(0xffffffffu, sum0, 2);
        sum1 += __shfl_xor_sync(0xffffffffu, sum1, 1);
        sum1 += __shfl_xor_sync(0xffffffffu, sum1, 2);

        l0 = l0 * f0 + sum0;
        l1 = l1 * f1 + sum1;
        m0 = mn0;
        m1 = mn1;
#pragma unroll
        for (int n = 0; n < 8; n++) {
            o[n][0] *= f0; o[n][1] *= f0;
            o[n][2] *= f1; o[n][3] *= f1;
        }
        __syncwarp();

        // --- O += P @ V  (A-frag reads P natural; B-frag reads V natural) ---
#pragma unroll
        for (int k = 0; k < 8; k++) {
            uint32_t ap0 = __float_as_uint(Ps[(mb + lg) * FST + k * 8 + lq]);
            uint32_t ap1 = __float_as_uint(Ps[(mb + 8 + lg) * FST + k * 8 + lq]);
            uint32_t ap2 = __float_as_uint(Ps[(mb + lg) * FST + k * 8 + lq + 4]);
            uint32_t ap3 = __float_as_uint(Ps[(mb + 8 + lg) * FST + k * 8 + lq + 4]);
#pragma unroll
            for (int n = 0; n < 8; n++) {
                uint32_t b0 = __float_as_uint(Vs[(k * 8 + lq) * FST + n * 8 + lg]);
                uint32_t b1 = __float_as_uint(Vs[(k * 8 + lq + 4) * FST + n * 8 + lg]);
                MMA_TF32(o[n], ap0, ap1, ap2, ap3, b0, b1);
            }
        }
        __syncthreads();   // all warps done with Ks/Vs before next chunk load
    }

    // --- epilogue: normalize and write y[B,S,D] head slice ---
    const float inv0 = 1.0f / l0;
    const float inv1 = 1.0f / l1;
#pragma unroll
    for (int n = 0; n < 8; n++) {
        const int col = h * HD + n * 8 + 2 * lq;
        float2 w0 = make_float2(o[n][0] * inv0, o[n][1] * inv0);
        float2 w1 = make_float2(o[n][2] * inv1, o[n][3] * inv1);
        *(float2*)(y_out + ((size_t)b * SS + r0g) * DD + col) = w0;
        *(float2*)(y_out + ((size_t)b * SS + r1g) * DD + col) = w1;
    }
}

// ---------------------------------------------------------------------------
// Launch
// ---------------------------------------------------------------------------
extern "C" void kernel_launch(void* const* d_in, const int* in_sizes, int n_in,
                              void* d_out, int out_size)
{
    (void)in_sizes; (void)n_in; (void)out_size;
    const float* x      = (const float*)d_in[0];
    const float* W_attn = (const float*)d_in[1];
    const float* b_attn = (const float*)d_in[2];
    const float* W_proj = (const float*)d_in[3];
    const float* b_proj = (const float*)d_in[4];
    float* out = (float*)d_out;

    float *qkv_ptr = nullptr, *y_ptr = nullptr;
    cudaGetSymbolAddress((void**)&qkv_ptr, g_qkv);
    cudaGetSymbolAddress((void**)&y_ptr, g_y);

    const int M = BB * SS;  // 8192
    cudaFuncSetAttribute(flash_mma_kernel,
                         cudaFuncAttributeMaxDynamicSharedMemorySize, FLASH_SMEM);

    // 1) QKV projection (tf32 mma.sync)
    {
        dim3 grid(3 * DD / 128, M / 128);
        hmma_gemm<<<grid, 256>>>(x, W_attn, b_attn, qkv_ptr, 3 * DD);
    }
    // 2) Causal flash attention (tf32 mma.sync)
    {
        dim3 grid(SS / 128, HH, BB);
        flash_mma_kernel<<<grid, 256, FLASH_SMEM>>>(y_ptr);
    }
    // 3) Output projection (tf32 mma.sync)
    {
        dim3 grid(DD / 128, M / 128);
        hmma_gemm<<<grid, 256>>>(y_ptr, W_proj, b_proj, out, DD);
    }
}

// round 5
// speedup vs baseline: 3.1768x; 1.0909x over previous
#include <cuda_runtime.h>
#include <math.h>
#include <stdint.h>

// Problem constants
#define BB 4
#define SS 2048
#define DD 1024
#define HH 16
#define HD 64
#define LOG2E 1.4426950408889634f

// Scratch (__device__ globals per allocation rules)
__device__ float g_qkv[(size_t)BB * SS * 3 * DD];   // [B,S,3D] (tf32-rounded)
__device__ float g_y[(size_t)BB * SS * DD];         // [B,S,D]  (tf32-rounded)
__device__ float g_xc[(size_t)BB * SS * DD];        // x, tf32-rounded
__device__ float g_wta[(size_t)3 * DD * DD];        // W_attn^T [3D][D], rounded
__device__ float g_wtp[(size_t)DD * DD];            // W_proj^T [D][D], rounded

__device__ __forceinline__ uint32_t cvt_tf32(float f) {
    uint32_t r;
    asm("cvt.rna.tf32.f32 %0, %1;" : "=r"(r) : "f"(f));
    return r;
}
__device__ __forceinline__ uint32_t smem_u32(const void* p) {
    uint32_t a;
    asm("{ .reg .u64 t; cvta.to.shared.u64 t, %1; cvt.u32.u64 %0, t; }" : "=r"(a) : "l"(p));
    return a;
}

#define MMA_TF32(acc, a0, a1, a2, a3, b0, b1) \
    asm volatile( \
        "mma.sync.aligned.m16n8k8.row.col.f32.tf32.tf32.f32 " \
        "{%0,%1,%2,%3}, {%4,%5,%6,%7}, {%8,%9}, {%0,%1,%2,%3};" \
        : "+f"((acc)[0]), "+f"((acc)[1]), "+f"((acc)[2]), "+f"((acc)[3]) \
        : "r"(a0), "r"(a1), "r"(a2), "r"(a3), "r"(b0), "r"(b1))

#define LDMX4(r0, r1, r2, r3, addr) \
    asm volatile("ldmatrix.sync.aligned.m8n8.x4.shared.b16 {%0,%1,%2,%3}, [%4];" \
        : "=r"(r0), "=r"(r1), "=r"(r2), "=r"(r3) : "r"(addr))

#define CP16(dst, src) \
    asm volatile("cp.async.cg.shared.global [%0], [%1], 16;" :: "r"(dst), "l"(src))
#define CP_COMMIT() asm volatile("cp.async.commit_group;" ::: "memory")
#define CP_WAIT(n)  asm volatile("cp.async.wait_group %0;" :: "n"(n) : "memory")

// ---------------------------------------------------------------------------
// Prep kernels
// ---------------------------------------------------------------------------
__global__ void cvt_round4(const float4* __restrict__ in, float4* __restrict__ out, int n4)
{
    int i = blockIdx.x * blockDim.x + threadIdx.x;
    if (i < n4) {
        float4 v = in[i];
        v.x = __uint_as_float(cvt_tf32(v.x));
        v.y = __uint_as_float(cvt_tf32(v.y));
        v.z = __uint_as_float(cvt_tf32(v.z));
        v.w = __uint_as_float(cvt_tf32(v.w));
        out[i] = v;
    }
}

// in[K][N] row-major -> out[N][K] row-major, tf32-rounded
__global__ void transpose_cvt(const float* __restrict__ in, float* __restrict__ out,
                              int K, int N)
{
    __shared__ float t[32][33];
    const int n0 = blockIdx.x * 32;
    const int k0 = blockIdx.y * 32;
#pragma unroll
    for (int i = 0; i < 32; i += 8)
        t[threadIdx.y + i][threadIdx.x] =
            in[(size_t)(k0 + threadIdx.y + i) * N + n0 + threadIdx.x];
    __syncthreads();
#pragma unroll
    for (int i = 0; i < 32; i += 8)
        out[(size_t)(n0 + threadIdx.y + i) * K + k0 + threadIdx.x] =
            __uint_as_float(cvt_tf32(t[threadIdx.x][threadIdx.y + i]));
}

// ---------------------------------------------------------------------------
// TF32 GEMM v2: C[M, Ntot] = A[M,1024] @ Wt[Ntot,1024]^T + bias
// CTA 128x256, 8 warps (2m x 4n), warp tile 64x64 (mt=4, nt=8).
// cp.async 3-stage pipeline; ldmatrix fragment loads; no cvt in mainloop.
// A smem [m][k], B smem [n][k], padded stride 20 floats.
// ---------------------------------------------------------------------------
#define GK 1024
#define KT 16
#define NKT (GK / KT)           // 64
#define GST 20                  // padded row stride (floats)
#define G_ASTAGE (128 * GST)    // 2560 floats
#define G_BSTAGE (256 * GST)    // 5120 floats
#define G_STAGE  (G_ASTAGE + G_BSTAGE)  // 7680 floats = 30720 B
#define GEMM_SMEM (3 * G_STAGE * 4)     // 92160 B

__global__ __launch_bounds__(256) void gemm_tc(
    const float* __restrict__ A, const float* __restrict__ Bt,
    const float* __restrict__ bias, float* __restrict__ C,
    int Ntot, int roundOut)
{
    extern __shared__ float gsm[];
    const uint32_t smb = smem_u32(gsm);

    const int tid = threadIdx.x;
    const int wid = tid >> 5;
    const int lane = tid & 31;
    const int lg = lane >> 2;
    const int lq = lane & 3;
    const int warp_m = wid & 1;       // 0..1 -> 64 rows
    const int warp_n = wid >> 1;      // 0..3 -> 64 cols
    const int mb = warp_m * 64;
    const int nbw = warp_n * 64;
    const int bn = blockIdx.x;
    const int bm = blockIdx.y;

    const float* Ag = A + (size_t)(bm * 128) * GK;
    const float* Bg = Bt + (size_t)(bn * 256) * GK;

    // cp.async source/dest indexing
    const int a_row = tid >> 2;             // 0..63 (+64 on second iter)
    const int a_c4 = (tid & 3) * 4;

    // ldmatrix lane-address offsets (floats)
    const int a_lm = (mb + (lane & 15)) * GST + ((lane >> 4) & 1) * 4;
    const int b_lm = (nbw + (lane & 7) + ((lane & 16) >> 1)) * GST + ((lane & 8) >> 1);

    float acc[4][8][4];
#pragma unroll
    for (int mt = 0; mt < 4; mt++)
#pragma unroll
        for (int nt = 0; nt < 8; nt++)
#pragma unroll
            for (int i = 0; i < 4; i++) acc[mt][nt][i] = 0.0f;

    // --- issue tile helper (as a macro over kt, stage) ---
#define G_ISSUE(kt_, st_) do {                                                  \
        const uint32_t sa_ = smb + ((st_) * G_STAGE) * 4;                       \
        const uint32_t sb_ = sa_ + G_ASTAGE * 4;                                \
        _Pragma("unroll")                                                       \
        for (int i_ = 0; i_ < 2; i_++) {                                        \
            const int row_ = a_row + i_ * 64;                                   \
            CP16(sa_ + (row_ * GST + a_c4) * 4,                                 \
                 Ag + (size_t)row_ * GK + (kt_) * KT + a_c4);                   \
        }                                                                       \
        _Pragma("unroll")                                                       \
        for (int i_ = 0; i_ < 4; i_++) {                                        \
            const int row_ = a_row + i_ * 64;                                   \
            CP16(sb_ + (row_ * GST + a_c4) * 4,                                 \
                 Bg + (size_t)row_ * GK + (kt_) * KT + a_c4);                   \
        }                                                                       \
    } while (0)

    G_ISSUE(0, 0); CP_COMMIT();
    G_ISSUE(1, 1); CP_COMMIT();

    for (int kt = 0; kt < NKT; kt++) {
        CP_WAIT(1);
        __syncthreads();
        if (kt + 2 < NKT) {
            const int st2 = (kt + 2) % 3;
            G_ISSUE(kt + 2, st2);
        }
        CP_COMMIT();

        const int st = kt % 3;
        const uint32_t sa = smb + (st * G_STAGE) * 4;
        const uint32_t sb = sa + G_ASTAGE * 4;

#pragma unroll
        for (int k8 = 0; k8 < 2; k8++) {
            const int k0 = k8 * 8;
            uint32_t af[4][4];
#pragma unroll
            for (int mt = 0; mt < 4; mt++)
                LDMX4(af[mt][0], af[mt][1], af[mt][2], af[mt][3],
                      sa + (a_lm + mt * 16 * GST + k0) * 4);
#pragma unroll
            for (int np = 0; np < 4; np++) {
                uint32_t b0, b1, b2, b3;
                LDMX4(b0, b1, b2, b3, sb + (b_lm + np * 16 * GST + k0) * 4);
#pragma unroll
                for (int mt = 0; mt < 4; mt++) {
                    MMA_TF32(acc[mt][2 * np], af[mt][0], af[mt][1], af[mt][2], af[mt][3], b0, b1);
                    MMA_TF32(acc[mt][2 * np + 1], af[mt][0], af[mt][1], af[mt][2], af[mt][3], b2, b3);
                }
            }
        }
    }
#undef G_ISSUE

    // epilogue
#pragma unroll
    for (int mt = 0; mt < 4; mt++) {
        const int row0 = bm * 128 + mb + mt * 16 + lg;
#pragma unroll
        for (int nt = 0; nt < 8; nt++) {
            const int col = bn * 256 + nbw + nt * 8 + 2 * lq;
            const float b0 = bias[col], b1 = bias[col + 1];
            float c0 = acc[mt][nt][0] + b0, c1 = acc[mt][nt][1] + b1;
            float c2 = acc[mt][nt][2] + b0, c3 = acc[mt][nt][3] + b1;
            if (roundOut) {
                c0 = __uint_as_float(cvt_tf32(c0));
                c1 = __uint_as_float(cvt_tf32(c1));
                c2 = __uint_as_float(cvt_tf32(c2));
                c3 = __uint_as_float(cvt_tf32(c3));
            }
            *(float2*)(C + (size_t)row0 * Ntot + col) = make_float2(c0, c1);
            *(float2*)(C + (size_t)(row0 + 8) * Ntot + col) = make_float2(c2, c3);
        }
    }
}

// ---------------------------------------------------------------------------
// Flash attention v2: tf32 mma, cp.async double-buffered K/V, ldmatrix frags.
// Q tile 128 rows (8 warps x m16), kv chunks of 64. Grid (S/128, H, B), 256 thr.
// smem floats: Qs/Ps [128][68] | stage0 {K,V} | stage1 {K,V}, each [64][68].
// ---------------------------------------------------------------------------
#define FST 68
#define F_QP (128 * FST)                 // 8704 floats
#define F_KV (64 * FST)                  // 4352 floats
#define F_STAGE (2 * F_KV)               // 8704 floats
#define FLASH_SMEM ((F_QP + 2 * F_STAGE) * 4)   // 104448 B

__global__ __launch_bounds__(256) void flash_mma_kernel(float* __restrict__ y_out)
{
    extern __shared__ float sm[];
    float* Qs = sm;          // reused as Ps
    float* Ps = sm;
    const uint32_t smb = smem_u32(sm);

    const int tid = threadIdx.x;
    const int wid = tid >> 5;
    const int lane = tid & 31;
    const int lg = lane >> 2;
    const int lq = lane & 3;
    const int mb = wid * 16;

    const int qt = blockIdx.x;
    const int h  = blockIdx.y;
    const int b  = blockIdx.z;
    const int q0 = qt * 128;

    const float* qkv = g_qkv;
    const size_t tokbase = (size_t)b * SS * 3 * DD;

    // --- Load Q tile [128 x 64] (pre-rounded) ---
#pragma unroll
    for (int i = 0; i < 8; i++) {
        const int idx = tid + i * 256;
        const int r = idx >> 4;
        const int d4 = (idx & 15) * 4;
        float4 v = *(const float4*)(qkv + tokbase + (size_t)(q0 + r) * (3 * DD) + h * HD + d4);
        *(float4*)&Qs[r * FST + d4] = v;
    }
    __syncthreads();

    // --- Hoist Q fragments ---
    uint32_t aq[8][4];
#pragma unroll
    for (int k = 0; k < 8; k++) {
        aq[k][0] = __float_as_uint(Qs[(mb + lg) * FST + k * 8 + lq]);
        aq[k][1] = __float_as_uint(Qs[(mb + 8 + lg) * FST + k * 8 + lq]);
        aq[k][2] = __float_as_uint(Qs[(mb + lg) * FST + k * 8 + lq + 4]);
        aq[k][3] = __float_as_uint(Qs[(mb + 8 + lg) * FST + k * 8 + lq + 4]);
    }
    __syncthreads();   // Qs free -> Ps

    float o[8][4];
#pragma unroll
    for (int n = 0; n < 8; n++)
#pragma unroll
        for (int i = 0; i < 4; i++) o[n][i] = 0.0f;
    float m0 = -1e30f, m1 = -1e30f, l0 = 0.0f, l1 = 0.0f;

    const int r0g = q0 + mb + lg;
    const int r1g = r0g + 8;
    const int nchunks = 2 * qt + 2;
    const float scale = 0.125f;

    // ldmatrix lane offsets (floats, within a K or P tile)
    const int k_lm = ((lane & 7) + ((lane & 16) >> 1)) * FST + ((lane & 8) >> 1);
    const int p_lm = (mb + (lane & 15)) * FST + ((lane >> 4) & 1) * 4;

    // cp.async chunk issue
    const int f_row = tid >> 4;           // 0..15 (+16,32,48)
    const int f_c4 = (tid & 15) * 4;

#define F_ISSUE(c_, st_) do {                                                    \
        const uint32_t kb_ = smb + (F_QP + (st_) * F_STAGE) * 4;                 \
        const int k0g_ = (c_) * 64;                                             \
        _Pragma("unroll")                                                        \
        for (int i_ = 0; i_ < 4; i_++) {                                         \
            const int row_ = f_row + i_ * 16;                                    \
            const float* src_ = qkv + tokbase + (size_t)(k0g_ + row_) * (3 * DD) \
                                + DD + h * HD + f_c4;                            \
            const uint32_t dst_ = kb_ + (row_ * FST + f_c4) * 4;                 \
            CP16(dst_, src_);                                                    \
            CP16(dst_ + F_KV * 4, src_ + DD);                                    \
        }                                                                        \
    } while (0)

    F_ISSUE(0, 0); CP_COMMIT();

    for (int c = 0; c < nchunks; c++) {
        const int st = c & 1;
        CP_WAIT(0);
        __syncthreads();
        if (c + 1 < nchunks) F_ISSUE(c + 1, st ^ 1);
        CP_COMMIT();

        const uint32_t ksb = smb + (F_QP + st * F_STAGE) * 4;
        const float* Vs = sm + F_QP + st * F_STAGE + F_KV;
        const int k0g = c * 64;

        // --- S = Q @ K^T via ldmatrix B-frags ---
        float s[8][4];
#pragma unroll
        for (int n = 0; n < 8; n++)
#pragma unroll
            for (int i = 0; i < 4; i++) s[n][i] = 0.0f;

#pragma unroll
        for (int k8 = 0; k8 < 8; k8++) {
#pragma unroll
            for (int np = 0; np < 4; np++) {
                uint32_t b0, b1, b2, b3;
                LDMX4(b0, b1, b2, b3, ksb + (k_lm + np * 16 * FST + k8 * 8) * 4);
                MMA_TF32(s[2 * np], aq[k8][0], aq[k8][1], aq[k8][2], aq[k8][3], b0, b1);
                MMA_TF32(s[2 * np + 1], aq[k8][0], aq[k8][1], aq[k8][2], aq[k8][3], b2, b3);
            }
        }

        // --- scale + causal mask ---
        if (c >= 2 * qt) {
#pragma unroll
            for (int n = 0; n < 8; n++) {
                const int col = k0g + n * 8 + 2 * lq;
                s[n][0] = (col     > r0g) ? -1e30f : s[n][0] * scale;
                s[n][1] = (col + 1 > r0g) ? -1e30f : s[n][1] * scale;
                s[n][2] = (col     > r1g) ? -1e30f : s[n][2] * scale;
                s[n][3] = (col + 1 > r1g) ? -1e30f : s[n][3] * scale;
            }
        } else {
#pragma unroll
            for (int n = 0; n < 8; n++)
#pragma unroll
                for (int i = 0; i < 4; i++) s[n][i] *= scale;
        }

        // --- online softmax ---
        float mx0 = -1e30f, mx1 = -1e30f;
#pragma unroll
        for (int n = 0; n < 8; n++) {
            mx0 = fmaxf(mx0, fmaxf(s[n][0], s[n][1]));
            mx1 = fmaxf(mx1, fmaxf(s[n][2], s[n][3]));
        }
        mx0 = fmaxf(mx0, __shfl_xor_sync(0xffffffffu, mx0, 1));
        mx0 = fmaxf(mx0, __shfl_xor_sync(0xffffffffu, mx0, 2));
        mx1 = fmaxf(mx1, __shfl_xor_sync(0xffffffffu, mx1, 1));
        mx1 = fmaxf(mx1, __shfl_xor_sync(0xffffffffu, mx1, 2));

        const float mn0 = fmaxf(m0, mx0);
        const float mn1 = fmaxf(m1, mx1);
        const float f0 = exp2f((m0 - mn0) * LOG2E);
        const float f1 = exp2f((m1 - mn1) * LOG2E);

        float sum0 = 0.0f, sum1 = 0.0f;
#pragma unroll
        for (int n = 0; n < 8; n++) {
            float p0 = exp2f((s[n][0] - mn0) * LOG2E);
            float p1 = exp2f((s[n][1] - mn0) * LOG2E);
            float p2 = exp2f((s[n][2] - mn1) * LOG2E);
            float p3 = exp2f((s[n][3] - mn1) * LOG2E);
            sum0 += p0 + p1;
            sum1 += p2 + p3;
            float2 w0 = make_float2(__uint_as_float(cvt_tf32(p0)), __uint_as_float(cvt_tf32(p1)));
            float2 w1 = make_float2(__uint_as_float(cvt_tf32(p2)), __uint_as_float(cvt_tf32(p3)));
            *(float2*)&Ps[(mb + lg) * FST + n * 8 + 2 * lq] = w0;
            *(float2*)&Ps[(mb + 8 + lg) * FST + n * 8 + 2 * lq] = w1;
        }
        sum0 += __shfl_xor_sync(0xffffffffu, sum0, 1);
        sum0 += __shfl_xor_sync(0xffffffffu, sum0, 2);
        sum1 += __shfl_xor_sync(0xffffffffu, sum1, 1);
        sum1 += __shfl_xor_sync(0xffffffffu, sum1, 2);

        l0 = l0 * f0 + sum0;
        l1 = l1 * f1 + sum1;
        m0 = mn0;
        m1 = mn1;
#pragma unroll
        for (int n = 0; n < 8; n++) {
            o[n][0] *= f0; o[n][1] *= f0;
            o[n][2] *= f1; o[n][3] *= f1;
        }
        __syncwarp();

        // --- O += P @ V  (P frags via ldmatrix; V frags via LDS) ---
#pragma unroll
        for (int k8 = 0; k8 < 8; k8++) {
            uint32_t ap0, ap1, ap2, ap3;
            LDMX4(ap0, ap1, ap2, ap3, smb + (p_lm + k8 * 8) * 4);
#pragma unroll
            for (int n = 0; n < 8; n++) {
                uint32_t b0 = __float_as_uint(Vs[(k8 * 8 + lq) * FST + n * 8 + lg]);
                uint32_t b1 = __float_as_uint(Vs[(k8 * 8 + lq + 4) * FST + n * 8 + lg]);
                MMA_TF32(o[n], ap0, ap1, ap2, ap3, b0, b1);
            }
        }
        // (next iteration's top __syncthreads orders stage reuse)
    }
#undef F_ISSUE

    // --- epilogue: normalize, round to tf32 (feeds proj GEMM), write y ---
    const float inv0 = 1.0f / l0;
    const float inv1 = 1.0f / l1;
#pragma unroll
    for (int n = 0; n < 8; n++) {
        const int col = h * HD + n * 8 + 2 * lq;
        float2 w0 = make_float2(__uint_as_float(cvt_tf32(o[n][0] * inv0)),
                                __uint_as_float(cvt_tf32(o[n][1] * inv0)));
        float2 w1 = make_float2(__uint_as_float(cvt_tf32(o[n][2] * inv1)),
                                __uint_as_float(cvt_tf32(o[n][3] * inv1)));
        *(float2*)(y_out + ((size_t)b * SS + r0g) * DD + col) = w0;
        *(float2*)(y_out + ((size_t)b * SS + r1g) * DD + col) = w1;
    }
}

// ---------------------------------------------------------------------------
// Launch
// ---------------------------------------------------------------------------
extern "C" void kernel_launch(void* const* d_in, const int* in_sizes, int n_in,
                              void* d_out, int out_size)
{
    (void)in_sizes; (void)n_in; (void)out_size;
    const float* x      = (const float*)d_in[0];
    const float* W_attn = (const float*)d_in[1];
    const float* b_attn = (const float*)d_in[2];
    const float* W_proj = (const float*)d_in[3];
    const float* b_proj = (const float*)d_in[4];
    float* out = (float*)d_out;

    float *qkv_p, *y_p, *xc_p, *wta_p, *wtp_p;
    cudaGetSymbolAddress((void**)&qkv_p, g_qkv);
    cudaGetSymbolAddress((void**)&y_p, g_y);
    cudaGetSymbolAddress((void**)&xc_p, g_xc);
    cudaGetSymbolAddress((void**)&wta_p, g_wta);
    cudaGetSymbolAddress((void**)&wtp_p, g_wtp);

    const int M = BB * SS;  // 8192
    cudaFuncSetAttribute(gemm_tc, cudaFuncAttributeMaxDynamicSharedMemorySize, GEMM_SMEM);
    cudaFuncSetAttribute(flash_mma_kernel, cudaFuncAttributeMaxDynamicSharedMemorySize, FLASH_SMEM);

    // 0) Prep: round x; transpose+round weights
    {
        const int n4 = M * DD / 4;   // 2,097,152
        cvt_round4<<<n4 / 256, 256>>>((const float4*)x, (float4*)xc_p, n4);
        dim3 tb(32, 8);
        transpose_cvt<<<dim3(3 * DD / 32, DD / 32), tb>>>(W_attn, wta_p, DD, 3 * DD);
        transpose_cvt<<<dim3(DD / 32, DD / 32), tb>>>(W_proj, wtp_p, DD, DD);
    }
    // 1) QKV projection (rounds output for flash)
    {
        dim3 grid(3 * DD / 256, M / 128);
        gemm_tc<<<grid, 256, GEMM_SMEM>>>(xc_p, wta_p, b_attn, qkv_p, 3 * DD, 1);
    }
    // 2) Causal flash attention
    {
        dim3 grid(SS / 128, HH, BB);
        flash_mma_kernel<<<grid, 256, FLASH_SMEM>>>(y_p);
    }
    // 3) Output projection (fp32 output, no rounding)
    {
        dim3 grid(DD / 256, M / 128);
        gemm_tc<<<grid, 256, GEMM_SMEM>>>(y_p, wtp_p, b_proj, out, DD, 0);
    }
}